// round 1
// baseline (speedup 1.0000x reference)
#include <cuda_runtime.h>
#include <math.h>

// ---------------------------------------------------------------------------
// AccuracyMetricLoss: per-day relative-RMS score, averaged over days.
//   denom = max(t, 0.2*cap); rel = (t-p)/denom
//   score_day = (1 - sqrt(mean_96(rel^2))) * 100
//   out = mean_days(score_day)
//
// Layout: t/p reshaped [days, 96] -> day d occupies 96 contiguous floats.
// Strategy: one warp per day (grid-stride). Lane l loads elems l, l+32, l+64
// -> fully coalesced. Warp shuffle reduce -> per-day score -> local fp32
// accumulate -> block reduce -> deterministic per-block partial (overwritten
// every launch, so no zeroing pass, graph-replay safe). Finalize kernel
// reduces the 2048 partials.
// ---------------------------------------------------------------------------

#define T_PERIODS   96
#define NBLOCKS     2048
#define NTHREADS    256
#define WARPS_PER_BLOCK (NTHREADS / 32)

// cap = (300+400+900)/300/1000 * 300400.0 = 1602.1333333333334
// thresh = 0.2f * (float)cap  (matches jnp.float32 promotion closely enough)
#define THRESH 320.4266666666667f

__device__ float g_partials[NBLOCKS];

__global__ void __launch_bounds__(NTHREADS)
day_score_kernel(const float* __restrict__ pred,
                 const float* __restrict__ tru,
                 int num_days)
{
    const int lane      = threadIdx.x & 31;
    const int warp_glob = (blockIdx.x * NTHREADS + threadIdx.x) >> 5;
    const int nwarps    = (NBLOCKS * NTHREADS) >> 5;

    float acc = 0.0f;

    for (int d = warp_glob; d < num_days; d += nwarps) {
        const float* tp = tru  + (size_t)d * T_PERIODS;
        const float* pp = pred + (size_t)d * T_PERIODS;

        float s = 0.0f;
        #pragma unroll
        for (int i = 0; i < 3; ++i) {
            float tv = __ldg(tp + lane + 32 * i);
            float pv = __ldg(pp + lane + 32 * i);
            float denom = fmaxf(tv, THRESH);
            float r = (tv - pv) / denom;
            s = fmaf(r, r, s);
        }
        // warp tree reduce (all lanes end with the full sum)
        #pragma unroll
        for (int o = 16; o > 0; o >>= 1)
            s += __shfl_xor_sync(0xFFFFFFFFu, s, o);

        acc += (1.0f - sqrtf(s * (1.0f / 96.0f))) * 100.0f;
    }

    // block reduce: one value per warp (all lanes of a warp hold the same acc)
    __shared__ float sh[WARPS_PER_BLOCK];
    if (lane == 0) sh[threadIdx.x >> 5] = acc;
    __syncthreads();

    if (threadIdx.x < WARPS_PER_BLOCK) {
        float v = sh[threadIdx.x];
        #pragma unroll
        for (int o = WARPS_PER_BLOCK / 2; o > 0; o >>= 1)
            v += __shfl_xor_sync((1u << WARPS_PER_BLOCK) - 1u, v, o);
        if (threadIdx.x == 0) g_partials[blockIdx.x] = v;
    }
}

__global__ void __launch_bounds__(1024)
finalize_kernel(float* __restrict__ out, int num_days)
{
    const int tid = threadIdx.x;
    float v = g_partials[tid] + g_partials[tid + 1024];

    __shared__ float sh[32];
    #pragma unroll
    for (int o = 16; o > 0; o >>= 1)
        v += __shfl_xor_sync(0xFFFFFFFFu, v, o);
    if ((tid & 31) == 0) sh[tid >> 5] = v;
    __syncthreads();

    if (tid < 32) {
        v = sh[tid];
        #pragma unroll
        for (int o = 16; o > 0; o >>= 1)
            v += __shfl_xor_sync(0xFFFFFFFFu, v, o);
        if (tid == 0) out[0] = v / (float)num_days;
    }
}

extern "C" void kernel_launch(void* const* d_in, const int* in_sizes, int n_in,
                              void* d_out, int out_size)
{
    const float* pred = (const float*)d_in[0];
    const float* tru  = (const float*)d_in[1];
    float* out = (float*)d_out;

    int num_days = in_sizes[1] / T_PERIODS;

    day_score_kernel<<<NBLOCKS, NTHREADS>>>(pred, tru, num_days);
    finalize_kernel<<<1, 1024>>>(out, num_days);
}

// round 2
// speedup vs baseline: 1.4523x; 1.4523x over previous
#include <cuda_runtime.h>
#include <math.h>

// ---------------------------------------------------------------------------
// AccuracyMetricLoss — per-day relative-RMS score averaged over days.
//   denom = max(t, 0.2*cap); score_day = (1 - sqrt(mean_96(((t-p)/denom)^2)))*100
//   out = mean_days(score_day)
//
// R2 design:
//  * float4 loads; 8-lane group per day (24 float4/day, 3 per lane per array).
//    Each group reads whole 128B lines -> 100% DRAM sector utilization.
//  * 6 LDG.128 per lane per warp-iteration (4 days/warp-iter) -> high MLP.
//  * rcp.approx.f32 instead of precise divide (err << 1e-3 budget).
//  * 3-shuffle segmented butterfly (xor 4,2,1) instead of 5-deep full-warp.
//  * single kernel: per-block partials + atomic-counter last-block finalize
//    (deterministic summation tree; counter self-resets -> graph-replay safe).
// ---------------------------------------------------------------------------

#define T_PERIODS  96
#define NBLOCKS    1216          // 8 per SM on 152-SM GB300
#define NTHREADS   256
#define THRESH     320.4266666666667f

__device__ float        g_partials[NBLOCKS];
__device__ unsigned int g_count = 0;

__device__ __forceinline__ float rcp_fast(float x) {
    float y;
    asm("rcp.approx.f32 %0, %1;" : "=f"(y) : "f"(x));
    return y;
}

__device__ __forceinline__ float acc_rel4(float4 t, float4 p, float s) {
    float d, r;
    d = t.x - p.x; r = d * rcp_fast(fmaxf(t.x, THRESH)); s = fmaf(r, r, s);
    d = t.y - p.y; r = d * rcp_fast(fmaxf(t.y, THRESH)); s = fmaf(r, r, s);
    d = t.z - p.z; r = d * rcp_fast(fmaxf(t.z, THRESH)); s = fmaf(r, r, s);
    d = t.w - p.w; r = d * rcp_fast(fmaxf(t.w, THRESH)); s = fmaf(r, r, s);
    return s;
}

__global__ void __launch_bounds__(NTHREADS)
score_kernel(const float* __restrict__ pred,
             const float* __restrict__ tru,
             float* __restrict__ out,
             int num_days)
{
    const int lane = threadIdx.x & 31;
    const int sub  = lane & 7;           // position within 8-lane day group
    const int grp  = lane >> 3;          // which of 4 days this lane serves
    const int warp_glob = (blockIdx.x * NTHREADS + threadIdx.x) >> 5;
    const int nwarps    = (NBLOCKS * NTHREADS) >> 5;

    const float4* t4 = (const float4*)tru;
    const float4* p4 = (const float4*)pred;

    const int main_iters = num_days >> 2;     // 4 days per warp-iteration
    float acc = 0.0f;

    for (int it = warp_glob; it < main_iters; it += nwarps) {
        const int d = (it << 2) + grp;
        const size_t o = (size_t)d * 24 + sub;   // float4 index, lane reads o, o+8, o+16

        float4 t0 = t4[o], t1 = t4[o + 8], t2 = t4[o + 16];
        float4 q0 = p4[o], q1 = p4[o + 8], q2 = p4[o + 16];

        float s = 0.0f;
        s = acc_rel4(t0, q0, s);
        s = acc_rel4(t1, q1, s);
        s = acc_rel4(t2, q2, s);

        // butterfly over the 8-lane group: all 8 lanes end with the day sum
        s += __shfl_xor_sync(0xFFFFFFFFu, s, 4);
        s += __shfl_xor_sync(0xFFFFFFFFu, s, 2);
        s += __shfl_xor_sync(0xFFFFFFFFu, s, 1);

        if (sub == 0)   // one lane per group contributes the day's score
            acc += (1.0f - sqrtf(s * (1.0f / 96.0f))) * 100.0f;
    }

    // tail days (num_days % 4) — scalar warp-per-day path on global warp 0
    if (warp_glob == 0) {
        for (int d = main_iters << 2; d < num_days; ++d) {
            float s = 0.0f;
            #pragma unroll
            for (int i = 0; i < 3; ++i) {
                float tv = tru [(size_t)d * T_PERIODS + lane + 32 * i];
                float pv = pred[(size_t)d * T_PERIODS + lane + 32 * i];
                float r = (tv - pv) * rcp_fast(fmaxf(tv, THRESH));
                s = fmaf(r, r, s);
            }
            #pragma unroll
            for (int o2 = 16; o2 > 0; o2 >>= 1)
                s += __shfl_xor_sync(0xFFFFFFFFu, s, o2);
            if (lane == 0)
                acc += (1.0f - sqrtf(s * (1.0f / 96.0f))) * 100.0f;
        }
    }

    // full-warp butterfly: sums the (mostly zero) lane accumulators
    #pragma unroll
    for (int o2 = 16; o2 > 0; o2 >>= 1)
        acc += __shfl_xor_sync(0xFFFFFFFFu, acc, o2);

    __shared__ float sh[NTHREADS / 32];
    if (lane == 0) sh[threadIdx.x >> 5] = acc;
    __syncthreads();

    __shared__ bool is_last;
    if (threadIdx.x == 0) {
        float v = 0.0f;
        #pragma unroll
        for (int w = 0; w < NTHREADS / 32; ++w) v += sh[w];
        g_partials[blockIdx.x] = v;
        __threadfence();
        unsigned c = atomicAdd(&g_count, 1u);
        is_last = (c == NBLOCKS - 1);
    }
    __syncthreads();

    if (is_last) {
        // deterministic finalize: fixed tree over the 1216 partials
        float v = 0.0f;
        for (int i = threadIdx.x; i < NBLOCKS; i += NTHREADS)
            v += __ldcg(&g_partials[i]);

        #pragma unroll
        for (int o2 = 16; o2 > 0; o2 >>= 1)
            v += __shfl_xor_sync(0xFFFFFFFFu, v, o2);
        if (lane == 0) sh[threadIdx.x >> 5] = v;
        __syncthreads();

        if (threadIdx.x < 32) {
            float w = (threadIdx.x < NTHREADS / 32) ? sh[threadIdx.x] : 0.0f;
            #pragma unroll
            for (int o2 = 4; o2 > 0; o2 >>= 1)
                w += __shfl_xor_sync(0xFFFFFFFFu, w, o2);
            if (threadIdx.x == 0) {
                out[0] = w / (float)num_days;
                g_count = 0;   // reset for next graph replay
            }
        }
    }
}

extern "C" void kernel_launch(void* const* d_in, const int* in_sizes, int n_in,
                              void* d_out, int out_size)
{
    const float* pred = (const float*)d_in[0];
    const float* tru  = (const float*)d_in[1];
    float* out = (float*)d_out;

    int num_days = in_sizes[1] / T_PERIODS;

    score_kernel<<<NBLOCKS, NTHREADS>>>(pred, tru, out, num_days);
}

// round 3
// speedup vs baseline: 1.4817x; 1.0202x over previous
#include <cuda_runtime.h>
#include <math.h>

// ---------------------------------------------------------------------------
// AccuracyMetricLoss — per-day relative-RMS score averaged over days.
//   denom = max(t, 0.2*cap); score_day = (1 - sqrt(mean_96(((t-p)/denom)^2)))*100
//   out = mean_days(score_day)
//
// R3 design:
//  * 8-lane group per day, float4 loads (whole 128B lines, 100% sectors).
//  * CONTIGUOUS day chunk per warp (perfect balance: 4736 warps x ~10.6
//    iterations each, vs R2's 38912 warps x 1.3 -> no wave quantization).
//  * Manual 2x unroll: 12 LDG.128 (6KB) in flight per warp per loop body;
//    the two groups' shuffle chains interleave to hide SHFL latency.
//  * rcp.approx.f32; fused atomic-counter last-block finalize (deterministic,
//    counter self-resets -> graph-replay safe).
// ---------------------------------------------------------------------------

#define T_PERIODS   96
#define NBLOCKS     296            // 2 blocks/SM on 148-SM floor
#define NTHREADS    512
#define TOTAL_WARPS (NBLOCKS * NTHREADS / 32)   // 4736
#define THRESH      320.4266666666667f

__device__ float        g_partials[NBLOCKS];
__device__ unsigned int g_count = 0;

__device__ __forceinline__ float rcp_fast(float x) {
    float y;
    asm("rcp.approx.f32 %0, %1;" : "=f"(y) : "f"(x));
    return y;
}

__device__ __forceinline__ float acc_rel4(float4 t, float4 p, float s) {
    float d, r;
    d = t.x - p.x; r = d * rcp_fast(fmaxf(t.x, THRESH)); s = fmaf(r, r, s);
    d = t.y - p.y; r = d * rcp_fast(fmaxf(t.y, THRESH)); s = fmaf(r, r, s);
    d = t.z - p.z; r = d * rcp_fast(fmaxf(t.z, THRESH)); s = fmaf(r, r, s);
    d = t.w - p.w; r = d * rcp_fast(fmaxf(t.w, THRESH)); s = fmaf(r, r, s);
    return s;
}

__device__ __forceinline__ float day_score(float s) {
    return (1.0f - sqrtf(s * (1.0f / 96.0f))) * 100.0f;
}

__global__ void __launch_bounds__(NTHREADS)
score_kernel(const float* __restrict__ pred,
             const float* __restrict__ tru,
             float* __restrict__ out,
             int num_days)
{
    const int lane = threadIdx.x & 31;
    const int sub  = lane & 7;            // position within 8-lane day group
    const int grp  = lane >> 3;           // which of 4 days this lane serves
    const int wid  = blockIdx.x * (NTHREADS / 32) + (threadIdx.x >> 5);

    const float4* t4 = (const float4*)tru;
    const float4* p4 = (const float4*)pred;

    // contiguous chunk of 4-day iterations per warp (balanced +/-1)
    const int nit = num_days >> 2;
    const int q   = nit / TOTAL_WARPS;
    const int r   = nit % TOTAL_WARPS;
    const int beg = wid * q + min(wid, r);
    const int end = beg + q + (wid < r ? 1 : 0);

    float acc = 0.0f;
    // float4 index this lane reads for iteration `it`: it*96 + grp*24 + sub
    size_t o = (size_t)beg * 96 + grp * 24 + sub;

    int it = beg;
    for (; it + 2 <= end; it += 2, o += 192) {
        // front-batch 12 independent LDG.128 (6 KB/warp in flight)
        float4 ta0 = t4[o],      ta1 = t4[o + 8],   ta2 = t4[o + 16];
        float4 tb0 = t4[o + 96], tb1 = t4[o + 104], tb2 = t4[o + 112];
        float4 qa0 = p4[o],      qa1 = p4[o + 8],   qa2 = p4[o + 16];
        float4 qb0 = p4[o + 96], qb1 = p4[o + 104], qb2 = p4[o + 112];

        float s0 = 0.0f, s1 = 0.0f;
        s0 = acc_rel4(ta0, qa0, s0); s1 = acc_rel4(tb0, qb0, s1);
        s0 = acc_rel4(ta1, qa1, s0); s1 = acc_rel4(tb1, qb1, s1);
        s0 = acc_rel4(ta2, qa2, s0); s1 = acc_rel4(tb2, qb2, s1);

        // interleaved 8-lane butterflies (independent -> latency overlap)
        s0 += __shfl_xor_sync(0xFFFFFFFFu, s0, 4);
        s1 += __shfl_xor_sync(0xFFFFFFFFu, s1, 4);
        s0 += __shfl_xor_sync(0xFFFFFFFFu, s0, 2);
        s1 += __shfl_xor_sync(0xFFFFFFFFu, s1, 2);
        s0 += __shfl_xor_sync(0xFFFFFFFFu, s0, 1);
        s1 += __shfl_xor_sync(0xFFFFFFFFu, s1, 1);

        if (sub == 0)
            acc += day_score(s0) + day_score(s1);
    }
    if (it < end) {   // odd leftover iteration
        float4 t0 = t4[o], t1 = t4[o + 8], t2 = t4[o + 16];
        float4 q0 = p4[o], q1 = p4[o + 8], q2 = p4[o + 16];
        float s = 0.0f;
        s = acc_rel4(t0, q0, s);
        s = acc_rel4(t1, q1, s);
        s = acc_rel4(t2, q2, s);
        s += __shfl_xor_sync(0xFFFFFFFFu, s, 4);
        s += __shfl_xor_sync(0xFFFFFFFFu, s, 2);
        s += __shfl_xor_sync(0xFFFFFFFFu, s, 1);
        if (sub == 0) acc += day_score(s);
    }

    // tail days (num_days % 4) — scalar warp-per-day path on global warp 0
    if (wid == 0) {
        for (int d = nit << 2; d < num_days; ++d) {
            float s = 0.0f;
            #pragma unroll
            for (int i = 0; i < 3; ++i) {
                float tv = tru [(size_t)d * T_PERIODS + lane + 32 * i];
                float pv = pred[(size_t)d * T_PERIODS + lane + 32 * i];
                float rr = (tv - pv) * rcp_fast(fmaxf(tv, THRESH));
                s = fmaf(rr, rr, s);
            }
            #pragma unroll
            for (int o2 = 16; o2 > 0; o2 >>= 1)
                s += __shfl_xor_sync(0xFFFFFFFFu, s, o2);
            if (lane == 0) acc += day_score(s);
        }
    }

    // warp butterfly over lane accumulators (only sub==0 lanes are nonzero)
    #pragma unroll
    for (int o2 = 16; o2 > 0; o2 >>= 1)
        acc += __shfl_xor_sync(0xFFFFFFFFu, acc, o2);

    __shared__ float sh[NTHREADS / 32];
    if (lane == 0) sh[threadIdx.x >> 5] = acc;
    __syncthreads();

    __shared__ bool is_last;
    if (threadIdx.x == 0) {
        float v = 0.0f;
        #pragma unroll
        for (int w = 0; w < NTHREADS / 32; ++w) v += sh[w];
        g_partials[blockIdx.x] = v;
        __threadfence();
        unsigned c = atomicAdd(&g_count, 1u);
        is_last = (c == NBLOCKS - 1);
    }
    __syncthreads();

    if (is_last) {
        float v = 0.0f;
        for (int i = threadIdx.x; i < NBLOCKS; i += NTHREADS)
            v += __ldcg(&g_partials[i]);

        #pragma unroll
        for (int o2 = 16; o2 > 0; o2 >>= 1)
            v += __shfl_xor_sync(0xFFFFFFFFu, v, o2);
        if (lane == 0) sh[threadIdx.x >> 5] = v;
        __syncthreads();

        if (threadIdx.x < 32) {
            float w = (threadIdx.x < NTHREADS / 32) ? sh[threadIdx.x] : 0.0f;
            #pragma unroll
            for (int o2 = 16; o2 > 0; o2 >>= 1)
                w += __shfl_xor_sync(0xFFFFFFFFu, w, o2);
            if (threadIdx.x == 0) {
                out[0] = w / (float)num_days;
                g_count = 0;   // reset for next graph replay
            }
        }
    }
}

extern "C" void kernel_launch(void* const* d_in, const int* in_sizes, int n_in,
                              void* d_out, int out_size)
{
    const float* pred = (const float*)d_in[0];
    const float* tru  = (const float*)d_in[1];
    float* out = (float*)d_out;

    int num_days = in_sizes[1] / T_PERIODS;

    score_kernel<<<NBLOCKS, NTHREADS>>>(pred, tru, out, num_days);
}

// round 5
// speedup vs baseline: 1.6463x; 1.1111x over previous
#include <cuda_runtime.h>
#include <math.h>

// ---------------------------------------------------------------------------
// AccuracyMetricLoss — per-day relative-RMS score averaged over days.
//   denom = max(t, 0.2*cap); score_day = (1 - sqrt(mean_96(((t-p)/denom)^2)))*100
//   out = mean_days(score_day)
//
// R4 design:
//  * 100% occupancy: 608 blocks x 512 thr (4 blocks/SM x 152 SMs), regs<=32
//    forced via __launch_bounds__(512,4)  -> 2x in-flight load bytes vs R3.
//  * Day-granular contiguous chunk per warp (+-1 day = +-4.9% quantization);
//    per-warp 0-3 day tail via predicated masked-group pass (uniform shfl).
//  * 8-lane group per day, float4 __ldcs streaming loads (evict-first; data
//    is single-pass 153.6MB > 126MB L2).
//  * 2x-unrolled body: 12 LDG.128 (6KB/warp) fronted per body.
//  * rcp.approx.f32; fused atomic-counter last-block finalize (deterministic
//    tree, counter self-resets -> graph-replay safe).
// ---------------------------------------------------------------------------

#define T_PERIODS   96
#define NBLOCKS     608            // 4 blocks/SM on 152 SMs
#define NTHREADS    512
#define TOTAL_WARPS (NBLOCKS * NTHREADS / 32)   // 9728
#define THRESH      320.4266666666667f

__device__ float        g_partials[NBLOCKS];
__device__ unsigned int g_count = 0;

__device__ __forceinline__ float rcp_fast(float x) {
    float y;
    asm("rcp.approx.f32 %0, %1;" : "=f"(y) : "f"(x));
    return y;
}

__device__ __forceinline__ float acc_rel4(float4 t, float4 p, float s) {
    float d, r;
    d = t.x - p.x; r = d * rcp_fast(fmaxf(t.x, THRESH)); s = fmaf(r, r, s);
    d = t.y - p.y; r = d * rcp_fast(fmaxf(t.y, THRESH)); s = fmaf(r, r, s);
    d = t.z - p.z; r = d * rcp_fast(fmaxf(t.z, THRESH)); s = fmaf(r, r, s);
    d = t.w - p.w; r = d * rcp_fast(fmaxf(t.w, THRESH)); s = fmaf(r, r, s);
    return s;
}

__device__ __forceinline__ float day_score(float s) {
    return (1.0f - sqrtf(s * (1.0f / 96.0f))) * 100.0f;
}

__global__ void __launch_bounds__(NTHREADS, 4)
score_kernel(const float* __restrict__ pred,
             const float* __restrict__ tru,
             float* __restrict__ out,
             int num_days)
{
    const int lane = threadIdx.x & 31;
    const int sub  = lane & 7;            // position within 8-lane day group
    const int grp  = lane >> 3;           // which of 4 days this lane serves
    const int wid  = blockIdx.x * (NTHREADS / 32) + (threadIdx.x >> 5);

    const float4* t4 = (const float4*)tru;
    const float4* p4 = (const float4*)pred;

    // contiguous DAY chunk per warp (lengths differ by at most 1 day)
    const int q   = num_days / TOTAL_WARPS;
    const int r   = num_days % TOTAL_WARPS;
    const int beg = wid * q + min(wid, r);
    const int end = beg + q + (wid < r ? 1 : 0);

    float acc = 0.0f;

    int d = beg;
    // lane's float4 index for the 4-day group starting at day d:
    //   (d + grp)*24 + sub   (then +8, +16 for the other two slots)
    size_t o = (size_t)(d + grp) * 24 + sub;

    // ---- 8-day unrolled body: 12 LDG.128 (6 KB/warp) in flight ----
    for (; d + 8 <= end; d += 8, o += 192) {
        float4 ta0 = __ldcs(&t4[o]),      ta1 = __ldcs(&t4[o + 8]),   ta2 = __ldcs(&t4[o + 16]);
        float4 tb0 = __ldcs(&t4[o + 96]), tb1 = __ldcs(&t4[o + 104]), tb2 = __ldcs(&t4[o + 112]);
        float4 qa0 = __ldcs(&p4[o]),      qa1 = __ldcs(&p4[o + 8]),   qa2 = __ldcs(&p4[o + 16]);
        float4 qb0 = __ldcs(&p4[o + 96]), qb1 = __ldcs(&p4[o + 104]), qb2 = __ldcs(&p4[o + 112]);

        float s0 = 0.0f, s1 = 0.0f;
        s0 = acc_rel4(ta0, qa0, s0); s1 = acc_rel4(tb0, qb0, s1);
        s0 = acc_rel4(ta1, qa1, s0); s1 = acc_rel4(tb1, qb1, s1);
        s0 = acc_rel4(ta2, qa2, s0); s1 = acc_rel4(tb2, qb2, s1);

        s0 += __shfl_xor_sync(0xFFFFFFFFu, s0, 4);
        s1 += __shfl_xor_sync(0xFFFFFFFFu, s1, 4);
        s0 += __shfl_xor_sync(0xFFFFFFFFu, s0, 2);
        s1 += __shfl_xor_sync(0xFFFFFFFFu, s1, 2);
        s0 += __shfl_xor_sync(0xFFFFFFFFu, s0, 1);
        s1 += __shfl_xor_sync(0xFFFFFFFFu, s1, 1);

        if (sub == 0)
            acc += day_score(s0) + day_score(s1);
    }

    // ---- single 4-day iteration ----
    if (d + 4 <= end) {
        float4 t0 = __ldcs(&t4[o]), t1 = __ldcs(&t4[o + 8]), t2 = __ldcs(&t4[o + 16]);
        float4 q0 = __ldcs(&p4[o]), q1 = __ldcs(&p4[o + 8]), q2 = __ldcs(&p4[o + 16]);
        float s = 0.0f;
        s = acc_rel4(t0, q0, s);
        s = acc_rel4(t1, q1, s);
        s = acc_rel4(t2, q2, s);
        s += __shfl_xor_sync(0xFFFFFFFFu, s, 4);
        s += __shfl_xor_sync(0xFFFFFFFFu, s, 2);
        s += __shfl_xor_sync(0xFFFFFFFFu, s, 1);
        if (sub == 0) acc += day_score(s);
        d += 4;
    }

    // ---- 0-3 leftover days: groups 0..rem-1 each take one day ----
    {
        const int rem = end - d;               // warp-uniform, 0..3
        if (rem > 0) {
            const int myday = d + (grp < rem ? grp : 0);   // clamp (valid addr)
            const size_t oo = (size_t)myday * 24 + sub;
            float4 t0 = __ldcs(&t4[oo]), t1 = __ldcs(&t4[oo + 8]), t2 = __ldcs(&t4[oo + 16]);
            float4 q0 = __ldcs(&p4[oo]), q1 = __ldcs(&p4[oo + 8]), q2 = __ldcs(&p4[oo + 16]);
            float s = 0.0f;
            s = acc_rel4(t0, q0, s);
            s = acc_rel4(t1, q1, s);
            s = acc_rel4(t2, q2, s);
            s += __shfl_xor_sync(0xFFFFFFFFu, s, 4);
            s += __shfl_xor_sync(0xFFFFFFFFu, s, 2);
            s += __shfl_xor_sync(0xFFFFFFFFu, s, 1);
            if (sub == 0 && grp < rem) acc += day_score(s);
        }
    }

    // warp butterfly over lane accumulators (only sub==0 lanes are nonzero)
    #pragma unroll
    for (int o2 = 16; o2 > 0; o2 >>= 1)
        acc += __shfl_xor_sync(0xFFFFFFFFu, acc, o2);

    __shared__ float sh[NTHREADS / 32];
    if (lane == 0) sh[threadIdx.x >> 5] = acc;
    __syncthreads();

    __shared__ bool is_last;
    if (threadIdx.x == 0) {
        float v = 0.0f;
        #pragma unroll
        for (int w = 0; w < NTHREADS / 32; ++w) v += sh[w];
        g_partials[blockIdx.x] = v;
        __threadfence();
        unsigned c = atomicAdd(&g_count, 1u);
        is_last = (c == NBLOCKS - 1);
    }
    __syncthreads();

    if (is_last) {
        // deterministic finalize: fixed tree over the 608 partials
        float v = 0.0f;
        for (int i = threadIdx.x; i < NBLOCKS; i += NTHREADS)
            v += __ldcg(&g_partials[i]);

        #pragma unroll
        for (int o2 = 16; o2 > 0; o2 >>= 1)
            v += __shfl_xor_sync(0xFFFFFFFFu, v, o2);
        if (lane == 0) sh[threadIdx.x >> 5] = v;
        __syncthreads();

        if (threadIdx.x < 32) {
            float w = (threadIdx.x < NTHREADS / 32) ? sh[threadIdx.x] : 0.0f;
            #pragma unroll
            for (int o2 = 16; o2 > 0; o2 >>= 1)
                w += __shfl_xor_sync(0xFFFFFFFFu, w, o2);
            if (threadIdx.x == 0) {
                out[0] = w / (float)num_days;
                g_count = 0;   // reset for next graph replay
            }
        }
    }
}

extern "C" void kernel_launch(void* const* d_in, const int* in_sizes, int n_in,
                              void* d_out, int out_size)
{
    const float* pred = (const float*)d_in[0];
    const float* tru  = (const float*)d_in[1];
    float* out = (float*)d_out;

    int num_days = in_sizes[1] / T_PERIODS;

    score_kernel<<<NBLOCKS, NTHREADS>>>(pred, tru, out, num_days);
}